// round 17
// baseline (speedup 1.0000x reference)
#include <cuda_runtime.h>
#include <cuda_fp16.h>
#include <cstdint>

#define Bn 64
#define Qn 2048
#define Kn 2048
#define Dn 128

// ---------------- scratch (device globals; no allocation) ----------------
__device__ __align__(256) __half g_qh[(size_t)Bn * Qn * Dn];          // Q fp16
__device__ __align__(256) __half g_kh[(size_t)Bn * Kn * Dn];          // K fp16
__device__ __align__(256) __half g_vth[(size_t)Bn * Dn * Kn];         // V^T fp16 [b][d][k]
__device__ __align__(256) __half g_e[(size_t)Bn * Qn * Kn];           // E fp16 (unnormalized)
__device__ __align__(256) float g_ps[(size_t)Bn * Qn * 32];   // partial sums per 64-col block
__device__ __align__(256) float g_is[(size_t)Bn * Qn];        // 1/row sum

// ---------------- helpers ----------------
#define MMA_F16(C, a0, a1, a2, a3, b0, b1)                                    \
  asm volatile(                                                               \
      "mma.sync.aligned.m16n8k16.row.col.f32.f16.f16.f32 "                    \
      "{%0,%1,%2,%3}, {%4,%5,%6,%7}, {%8,%9}, {%0,%1,%2,%3};\n"               \
      : "+f"(C[0]), "+f"(C[1]), "+f"(C[2]), "+f"(C[3])                        \
      : "r"(a0), "r"(a1), "r"(a2), "r"(a3), "r"(b0), "r"(b1))

#define LDSM_X4(r0, r1, r2, r3, a)                                            \
  asm volatile("ldmatrix.sync.aligned.m8n8.x4.shared.b16 {%0,%1,%2,%3}, [%4];" \
               : "=r"(r0), "=r"(r1), "=r"(r2), "=r"(r3) : "r"(a))

__device__ __forceinline__ uint32_t packh2(float x, float y) {
    __half2 h = __floats2half2_rn(x, y);
    return *reinterpret_cast<uint32_t*>(&h);
}
__device__ __forceinline__ uint32_t smem_u32(const void* p) {
    return (uint32_t)__cvta_generic_to_shared(p);
}
__device__ __forceinline__ void cpasync16(uint32_t dst, const void* src) {
    asm volatile("cp.async.cg.shared.global [%0], [%1], 16;\n" :: "r"(dst), "l"(src));
}
#define CP_COMMIT asm volatile("cp.async.commit_group;\n" ::: "memory")
#define CP_WAIT0  asm volatile("cp.async.wait_group 0;\n" ::: "memory")

// ================= K0a: fp32 -> fp16 =================
__global__ void __launch_bounds__(256)
convert1_kernel(const float* __restrict__ x, __half* __restrict__ h)
{
    int i = blockIdx.x * 256 + threadIdx.x;
    float4 v = ((const float4*)x)[i];
    ((uint2*)h)[i] = make_uint2(packh2(v.x, v.y), packh2(v.z, v.w));
}

// ================= K0b: V fp32 [b][k][d] -> fp16 [b][d][k] =================
__global__ void __launch_bounds__(256)
transpose_conv_kernel(const float* __restrict__ v, __half* __restrict__ th)
{
    __shared__ float t[32][33];
    const int b  = blockIdx.z;
    const int k0 = blockIdx.x * 32;
    const int d0 = blockIdx.y * 32;
    const int tx = threadIdx.x & 31;
    const int ty = threadIdx.x >> 5;
#pragma unroll
    for (int i = 0; i < 4; i++) {
        int k = ty + i * 8;
        t[k][tx] = v[((size_t)b * Kn + k0 + k) * Dn + d0 + tx];
    }
    __syncthreads();
#pragma unroll
    for (int i = 0; i < 4; i++) {
        int d = ty + i * 8;
        th[((size_t)b * Dn + d0 + d) * Kn + k0 + tx] = __float2half_rn(t[tx][d]);
    }
}

// ================= K1: E = exp(masked scores) -> fp16 + partial row sums =================
// 512 threads, CTA tile M=128 x N=256, 4-quarter cp.async pipeline,
// single-term fp16 mma; 104.4KB smem -> 2 CTAs/SM.
#define K1S 136                    /* fp16 row stride (272 B) */
#define OFF_QH 0
#define OFF_KH (128 * K1S * 2)                 /* 34816 */
#define K1_SMEM (OFF_KH + 256 * K1S * 2)       /* 104448 */
#define SC_SCALE 0.08838834764831845f

__global__ void __launch_bounds__(512, 2)
scores_kernel(const __half* __restrict__ qh, const __half* __restrict__ kh,
              const int* __restrict__ vlg,
              __half* __restrict__ eg, float* __restrict__ ps)
{
    extern __shared__ unsigned char sm[];
    __half* sQh = (__half*)(sm + OFF_QH);
    __half* sKh = (__half*)(sm + OFF_KH);
    const uint32_t uQh = smem_u32(sQh), uKh = smem_u32(sKh);

    const int b  = blockIdx.z;
    const int i0 = blockIdx.y * 128;
    const int j0 = blockIdx.x * 256;
    const int tid = threadIdx.x;
    const int w = tid >> 5, lane = tid & 31;
    const int g = lane >> 2, ct = lane & 3;
    const int wm = w >> 2, wn = w & 3;        // 4x4 warp grid, 32x64 warp tiles
    const int m0 = wm * 32, n0 = wn * 64;
    const int VL = vlg[b];

    const __half* bq = qh + ((size_t)b * Qn + i0) * Dn;
    const __half* bk = kh + ((size_t)b * Kn + j0) * Dn;

    // 4 commit groups, one per D-quarter (cols q*32 .. q*32+31)
#pragma unroll
    for (int q = 0; q < 4; q++) {
        {   // Q: 512 chunks
            int r = tid >> 2, cc = tid & 3;
            int dsto = r * (K1S * 2) + (q * 4 + cc) * 16;
            cpasync16(uQh + dsto, bq + (size_t)r * Dn + q * 32 + cc * 8);
        }
#pragma unroll
        for (int rep = 0; rep < 2; rep++) {   // K: 1024 chunks
            int idx = tid + rep * 512;
            int r = idx >> 2, cc = idx & 3;
            int dsto = r * (K1S * 2) + (q * 4 + cc) * 16;
            cpasync16(uKh + dsto, bk + (size_t)r * Dn + q * 32 + cc * 8);
        }
        CP_COMMIT;
    }

    float acc[2][8][4] = {};
#pragma unroll
    for (int q = 0; q < 4; q++) {
        if (q == 0)      asm volatile("cp.async.wait_group 3;\n" ::: "memory");
        else if (q == 1) asm volatile("cp.async.wait_group 2;\n" ::: "memory");
        else if (q == 2) asm volatile("cp.async.wait_group 1;\n" ::: "memory");
        else             asm volatile("cp.async.wait_group 0;\n" ::: "memory");
        __syncthreads();
#pragma unroll
        for (int kt = 0; kt < 2; kt++) {
            const int kk = q * 2 + kt;
            uint32_t ah[2][4];
#pragma unroll
            for (int mf = 0; mf < 2; mf++) {
                const __half* p0 = sQh + (m0 + mf * 16 + g) * K1S + kk * 16 + 2 * ct;
                ah[mf][0] = *(const uint32_t*)p0;
                ah[mf][1] = *(const uint32_t*)(p0 + 8 * K1S);
                ah[mf][2] = *(const uint32_t*)(p0 + 8);
                ah[mf][3] = *(const uint32_t*)(p0 + 8 * K1S + 8);
            }
#pragma unroll
            for (int nf = 0; nf < 8; nf++) {
                const __half* kb = sKh + (n0 + nf * 8 + g) * K1S + kk * 16 + 2 * ct;
                uint32_t bh0 = *(const uint32_t*)kb;
                uint32_t bh1 = *(const uint32_t*)(kb + 8);
#pragma unroll
                for (int mf = 0; mf < 2; mf++)
                    MMA_F16(acc[mf][nf], ah[mf][0], ah[mf][1], ah[mf][2], ah[mf][3], bh0, bh1);
            }
        }
    }

    // ---- epilogue: scale, mask, exp, fp16 E store, partial sums ----
    const float mval = (VL == 0) ? 1.0f : 0.0f;
    const int jt = blockIdx.x * 4 + wn;        // 64-col block id (0..31)
#pragma unroll
    for (int mf = 0; mf < 2; mf++) {
#pragma unroll
        for (int h = 0; h < 2; h++) {
            const int row = m0 + mf * 16 + h * 8 + g;
            __half* erow = eg + ((size_t)b * Qn + i0 + row) * Kn + j0 + n0;
            float se = 0.f;
#pragma unroll
            for (int nf = 0; nf < 8; nf++) {
                int j = j0 + n0 + nf * 8 + 2 * ct;
                float e0 = (j     < VL) ? __expf(acc[mf][nf][2 * h]     * SC_SCALE) : mval;
                float e1 = (j + 1 < VL) ? __expf(acc[mf][nf][2 * h + 1] * SC_SCALE) : mval;
                *(uint32_t*)(erow + nf * 8 + 2 * ct) = packh2(e0, e1);
                se += e0 + e1;
            }
            se += __shfl_xor_sync(0xffffffffu, se, 1);
            se += __shfl_xor_sync(0xffffffffu, se, 2);
            if (ct == 0)
                ps[((size_t)b * Qn + i0 + row) * 32 + jt] = se;
        }
    }
}

// ================= K1b: reduce partials -> 1/row sum =================
__global__ void __launch_bounds__(256)
reduce_kernel(const float* __restrict__ ps, float* __restrict__ iso)
{
    int i = blockIdx.x * 256 + threadIdx.x;
    const float4* s4 = (const float4*)(ps + (size_t)i * 32);
    float sum = 0.f;
#pragma unroll
    for (int t = 0; t < 8; t++) {
        float4 sv = s4[t];
        sum += (sv.x + sv.y) + (sv.z + sv.w);
    }
    iso[i] = 1.0f / sum;
}

// ================= K2: attn writeback + PV GEMM (single-term fp16) =================
#define PS2 72    /* fp16 stride, E tile (144 B row) */
#define VS 72     /* fp16 stride, Vt tile             */
#define K2_OFF_E  0
#define K2_OFF_VH (128 * PS2 * 2)          /* 18432 */
#define K2_OFF_IV (K2_OFF_VH + 128 * VS * 2)
#define K2_SMEM   (K2_OFF_IV + 128 * 4)    /* 37376 */

__global__ void __launch_bounds__(256, 2)
pv_kernel(const __half* __restrict__ eg, const __half* __restrict__ vth,
          const float* __restrict__ isg,
          float* __restrict__ att, float* __restrict__ outg)
{
    extern __shared__ unsigned char sm[];
    __half* sE  = (__half*)(sm + K2_OFF_E);
    __half* sVh = (__half*)(sm + K2_OFF_VH);
    float*  sIv = (float*)(sm + K2_OFF_IV);

    const int b  = blockIdx.y;
    const int i0 = blockIdx.x * 128;
    const int tid = threadIdx.x;
    const int w = tid >> 5, lane = tid & 31;
    const int g = lane >> 2, ct = lane & 3;
    const int wm = w >> 1, wn = w & 1;

    const __half* e_g = eg + ((size_t)b * Qn + i0) * Kn;
    const __half* vh_g = vth + (size_t)b * Dn * Kn;
    float* Ag = att + ((size_t)b * Qn + i0) * Kn;
    uint32_t uE  = smem_u32(sE);
    uint32_t uVh = smem_u32(sVh);

    if (tid < 128) sIv[tid] = isg[(size_t)b * Qn + i0 + tid];

    float ris[2][2];
#pragma unroll
    for (int mf = 0; mf < 2; mf++)
#pragma unroll
        for (int h = 0; h < 2; h++)
            ris[mf][h] = isg[(size_t)b * Qn + i0 + wm * 32 + mf * 16 + h * 8 + g];

    // ldmatrix bases
    const int lr = lane & 15;
    const int lc = (lane >> 4) << 3;
    const uint32_t aE  = uE  + ((wm * 32 + lr) * PS2 + lc) * 2;
    const uint32_t aVh = uVh + ((wn * 64 + lr) * VS + lc) * 2;
    const uint32_t MSTEP2 = 16 * PS2 * 2;   // 2304 bytes

    float acc[2][8][4] = {};

    for (int c0 = 0; c0 < Kn; c0 += 64) {
        __syncthreads();
        // E tile: 128 rows x 64 fp16
#pragma unroll
        for (int rep = 0; rep < 4; rep++) {
            int idx = tid + rep * 256;      // 0..1023 = 128 rows x 8 chunks
            int r = idx >> 3, c8 = idx & 7;
            cpasync16(uE + r * (PS2 * 2) + c8 * 16, e_g + (size_t)r * Kn + c0 + c8 * 8);
        }
        // Vt tile: 128 d-rows x 64 fp16
#pragma unroll
        for (int rep = 0; rep < 4; rep++) {
            int idx = tid + rep * 256;
            int d = idx >> 3, c8 = idx & 7;
            cpasync16(uVh + d * (VS * 2) + c8 * 16, vh_g + (size_t)d * Kn + c0 + c8 * 8);
        }
        CP_COMMIT; CP_WAIT0;
        __syncthreads();

        // attn writeback: attn = E * inv, coalesced float4 stores
#pragma unroll
        for (int rep = 0; rep < 8; rep++) {
            int idx = tid + rep * 256;      // 0..2047 = 128 rows x 16 quad-cols
            int r = idx >> 4, c4 = idx & 15;
            float iv = sIv[r];
            const __half2* ep = (const __half2*)(sE + r * PS2 + c4 * 4);
            float2 e0 = __half22float2(ep[0]);
            float2 e1 = __half22float2(ep[1]);
            float4 o;
            o.x = e0.x * iv;
            o.y = e0.y * iv;
            o.z = e1.x * iv;
            o.w = e1.y * iv;
            *(float4*)(Ag + (size_t)r * Kn + c0 + c4 * 4) = o;
        }

#pragma unroll
        for (int kk = 0; kk < 4; kk++) {
            const uint32_t co = kk * 32;
            uint32_t ah[2][4];
            LDSM_X4(ah[0][0], ah[0][1], ah[0][2], ah[0][3], aE + co);
            LDSM_X4(ah[1][0], ah[1][1], ah[1][2], ah[1][3], aE + MSTEP2 + co);
#pragma unroll
            for (int nf2 = 0; nf2 < 4; nf2++) {
                uint32_t bh[4];
                LDSM_X4(bh[0], bh[1], bh[2], bh[3], aVh + nf2 * MSTEP2 + co);
#pragma unroll
                for (int mf = 0; mf < 2; mf++) {
                    MMA_F16(acc[mf][2 * nf2],     ah[mf][0], ah[mf][1], ah[mf][2], ah[mf][3], bh[0], bh[2]);
                    MMA_F16(acc[mf][2 * nf2 + 1], ah[mf][0], ah[mf][1], ah[mf][2], ah[mf][3], bh[1], bh[3]);
                }
            }
        }
    }

    // out = acc * inv (normalization folded into accumulator epilogue)
    float* op = outg + ((size_t)b * Qn + i0) * Dn;
#pragma unroll
    for (int mf = 0; mf < 2; mf++)
#pragma unroll
        for (int nf = 0; nf < 8; nf++) {
            int row = wm * 32 + mf * 16 + g;
            int col = wn * 64 + nf * 8 + 2 * ct;
            float i0v = ris[mf][0], i1v = ris[mf][1];
            *(float2*)(op + (size_t)row * Dn + col) =
                make_float2(acc[mf][nf][0] * i0v, acc[mf][nf][1] * i0v);
            *(float2*)(op + (size_t)(row + 8) * Dn + col) =
                make_float2(acc[mf][nf][2] * i1v, acc[mf][nf][3] * i1v);
        }
}

// ================= launch =================
extern "C" void kernel_launch(void* const* d_in, const int* in_sizes, int n_in,
                              void* d_out, int out_size) {
    const float* q  = (const float*)d_in[0];
    const float* k  = (const float*)d_in[1];
    const float* v  = (const float*)d_in[2];
    const int*   vl = (const int*)d_in[3];
    float* out  = (float*)d_out;
    float* attn = out + (size_t)Bn * Qn * Dn;   // output tuple: (out, attn)

    void *p_qh, *p_kh, *p_vth, *p_e, *p_ps, *p_is;
    cudaGetSymbolAddress(&p_qh, g_qh);
    cudaGetSymbolAddress(&p_kh, g_kh);
    cudaGetSymbolAddress(&p_vth, g_vth);
    cudaGetSymbolAddress(&p_e,  g_e);
    cudaGetSymbolAddress(&p_ps, g_ps);
    cudaGetSymbolAddress(&p_is, g_is);

    cudaFuncSetAttribute(scores_kernel, cudaFuncAttributeMaxDynamicSharedMemorySize, K1_SMEM);
    cudaFuncSetAttribute(pv_kernel,     cudaFuncAttributeMaxDynamicSharedMemorySize, K2_SMEM);

    const int n4 = Bn * Qn * Dn / 4;
    convert1_kernel<<<n4 / 256, 256>>>(q, (__half*)p_qh);
    convert1_kernel<<<n4 / 256, 256>>>(k, (__half*)p_kh);
    transpose_conv_kernel<<<dim3(Kn / 32, Dn / 32, Bn), 256>>>(v, (__half*)p_vth);

    scores_kernel<<<dim3(Kn / 256, Qn / 128, Bn), 512, K1_SMEM>>>(
        (const __half*)p_qh, (const __half*)p_kh,
        vl, (__half*)p_e, (float*)p_ps);

    reduce_kernel<<<Bn * Qn / 256, 256>>>((const float*)p_ps, (float*)p_is);

    pv_kernel<<<dim3(Qn / 128, Bn), 256, K2_SMEM>>>(
        (const __half*)p_e, (const __half*)p_vth,
        (const float*)p_is, attn, out);
}